// round 9
// baseline (speedup 1.0000x reference)
#include <cuda_runtime.h>
#include <cuda_fp16.h>
#include <cstdint>

#define BATCH      256
#define INPUT_DIM  4096
#define SOMA       2048
#define BRANCH     16
#define NUM_DEND   (SOMA * BRANCH)   // 32768
#define SAMPLE     32
#define NEG        0.1f

#define BT         8                 // batches per block (4x half2 = 16B per x element)
#define NBG        (BATCH / BT)      // 32 batch groups
#define DT         512
#define NTHREADS   512

#define PREP_THREADS 256
#define XB   ((NBG * 2 * INPUT_DIM) / PREP_THREADS)   // 1024 blocks for x prep
#define PB   (NUM_DEND / PREP_THREADS)                // 128 blocks for pack prep

#define XS_BYTES (INPUT_DIM * 16)    // 64 KB

// Scratch (allocation-free rule: __device__ globals)
// pk word layout: [15:0] = w (fp16 bits), [31:16] = ix<<4 (byte offset, max 65520)
__device__ uint4  g_pk[(SAMPLE/4) * NUM_DEND];     // [s4][d], 4 MB
__device__ uint4  g_xprep[NBG * INPUT_DIM];        // [bg][i]: 8 batches as 4x half2, 2 MB

__device__ __forceinline__ uint32_t smem_u32(const void* p) {
    uint32_t a;
    asm("{ .reg .u64 t; cvta.to.shared.u64 t, %1; cvt.u32.u64 %0, t; }" : "=r"(a) : "l"(p));
    return a;
}

// ---- fused pre-pass: x packing (blocks < XB) + idx/w pack-sort (blocks >= XB) ----
__global__ void prep_fused(const float* __restrict__ x,
                           const int*   __restrict__ idx,
                           const float* __restrict__ sw)
{
    __shared__ unsigned buf[SAMPLE * PREP_THREADS];  // 32 KB (used by pack part)
    const int tid = threadIdx.x;

    if (blockIdx.x < XB) {
        // ---- pack x into batch-interleaved fp16 ----
        int t  = blockIdx.x * PREP_THREADS + tid;     // 0 .. NBG*2*INPUT_DIM-1
        int bg = t / (2 * INPUT_DIM);
        int r  = t - bg * 2 * INPUT_DIM;
        int h  = r / INPUT_DIM;
        int i  = r - h * INPUT_DIM;

        const float* xr = x + ((size_t)bg * BT + h * 4) * INPUT_DIM + i;
        __half2 a = __floats2half2_rn(xr[0],             xr[INPUT_DIM]);
        __half2 b = __floats2half2_rn(xr[2 * INPUT_DIM], xr[3 * INPUT_DIM]);
        uint2 v;
        v.x = *reinterpret_cast<unsigned*>(&a);
        v.y = *reinterpret_cast<unsigned*>(&b);
        reinterpret_cast<uint2*>(g_xprep)[(size_t)(bg * INPUT_DIM + i) * 2 + h] = v;
        return;
    }

    // ---- pack {off16 = ix<<4, w fp16} with FIXED-SLOT bank-class schedule ----
    const int d = (blockIdx.x - XB) * PREP_THREADS + tid;

    const int4*   ir = reinterpret_cast<const int4*>(idx) + (size_t)d * (SAMPLE/4);
    const float4* wr = reinterpret_cast<const float4*>(sw) + (size_t)d * (SAMPLE/4);

    // Load + pack all 32 elements (static indices -> registers)
    unsigned pkv[SAMPLE];
    #pragma unroll
    for (int s4 = 0; s4 < SAMPLE/4; ++s4) {
        const int4   i4 = ir[s4];
        const float4 w4 = wr[s4];
        #pragma unroll
        for (int q = 0; q < 4; ++q) {
            const int   ix = (q == 0) ? i4.x : (q == 1) ? i4.y : (q == 2) ? i4.z : i4.w;
            const float w  = (q == 0) ? w4.x : (q == 1) ? w4.y : (q == 2) ? w4.z : w4.w;
            pkv[4*s4 + q] = (unsigned)__half_as_ushort(__float2half_rn(w))
                          | ((unsigned)ix << 20);            // (ix<<4) in high 16
        }
    }

    // Pass A: class c (= ix&7 = bits [22:20]) owns slots 4c..4c+3
    unsigned long long fill = 0ull;
    unsigned unplaced = 0u;
    #pragma unroll
    for (int e = 0; e < SAMPLE; ++e) {
        const int c = (int)((pkv[e] >> 20) & 7u);
        const int p = (int)((fill >> (8 * c)) & 0xff);
        if (p < 4) {
            fill += 1ull << (8 * c);
            buf[(4 * c + p) * PREP_THREADS + tid] = pkv[e];
        } else {
            unplaced |= 1u << e;
        }
    }
    // Pass B: overflow fills deficit slots (static pkv indices)
    {
        int cslot = 0;
        #pragma unroll
        for (int e = 0; e < SAMPLE; ++e) {
            if ((unplaced >> e) & 1u) {
                while (((fill >> (8 * cslot)) & 0xffull) >= 4) ++cslot;
                const int p = (int)((fill >> (8 * cslot)) & 0xff);
                fill += 1ull << (8 * cslot);
                buf[(4 * cslot + p) * PREP_THREADS + tid] = pkv[e];
            }
        }
    }

    // Output with per-lane rotation so quarter-warp classes are staggered
    const int rot = 4 * (d & 7);
    #pragma unroll
    for (int s4 = 0; s4 < SAMPLE/4; ++s4) {
        uint4 p;
        p.x = buf[(((4*s4 + 0) + rot) & 31) * PREP_THREADS + tid];
        p.y = buf[(((4*s4 + 1) + rot) & 31) * PREP_THREADS + tid];
        p.z = buf[(((4*s4 + 2) + rot) & 31) * PREP_THREADS + tid];
        p.w = buf[(((4*s4 + 3) + rot) & 31) * PREP_THREADS + tid];
        g_pk[s4 * NUM_DEND + d] = p;
    }
}

// ---- main kernel ----
__global__ __launch_bounds__(NTHREADS, 2)
void dend_kernel(const float* __restrict__ sb,
                 const float* __restrict__ cw,
                 const float* __restrict__ somab,
                 float* __restrict__ soma_out,
                 float* __restrict__ dend_out)
{
    extern __shared__ uint4 xs[];   // [INPUT_DIM] = 64 KB
    __shared__ __align__(8) uint64_t mbar;

    const int bg  = blockIdx.y;
    const int b0  = bg * BT;
    const int d0  = blockIdx.x * DT;
    const int tid = threadIdx.x;

    const uint32_t mbar_a = smem_u32(&mbar);
    const uint32_t xs_a   = smem_u32(xs);

    if (tid == 0) {
        asm volatile("mbarrier.init.shared::cta.b64 [%0], 1;" :: "r"(mbar_a) : "memory");
    }
    __syncthreads();
    if (tid == 0) {
        asm volatile("mbarrier.arrive.expect_tx.shared::cta.b64 _, [%0], %1;"
                     :: "r"(mbar_a), "r"((unsigned)XS_BYTES) : "memory");
        asm volatile("cp.async.bulk.shared::cta.global.mbarrier::complete_tx::bytes "
                     "[%0], [%1], %2, [%3];"
                     :: "r"(xs_a), "l"(g_xprep + (size_t)bg * INPUT_DIM),
                        "r"((unsigned)XS_BYTES), "r"(mbar_a) : "memory");
    }

    const int d = d0 + tid;

    // Prefetch first pk + scalars while TMA fills smem
    const uint4 pk0  = g_pk[d];
    const float bias = sb[d];
    const float cwv  = cw[d];   // cable_weights flattened [soma][branch] == index d

    // Wait for bulk copy completion (phase 0)
    {
        unsigned done;
        asm volatile(
            "{\n\t.reg .pred p;\n\t"
            "mbarrier.try_wait.parity.acquire.cta.shared::cta.b64 p, [%1], 0;\n\t"
            "selp.b32 %0, 1, 0, p;\n\t}"
            : "=r"(done) : "r"(mbar_a) : "memory");
        while (!done) {
            asm volatile(
                "{\n\t.reg .pred p;\n\t"
                "mbarrier.try_wait.parity.acquire.cta.shared::cta.b64 p, [%1], 0, 0x989680;\n\t"
                "selp.b32 %0, 1, 0, p;\n\t}"
                : "=r"(done) : "r"(mbar_a) : "memory");
        }
    }

    // Packed f32x2 accumulators
    uint64_t acc01 = 0ull, acc23 = 0ull, acc45 = 0ull, acc67 = 0ull;

    #pragma unroll
    for (int s4 = 0; s4 < SAMPLE / 4; ++s4) {
        const uint4 pk = (s4 == 0) ? pk0 : g_pk[s4 * NUM_DEND + d];   // coalesced

        #pragma unroll
        for (int q = 0; q < 4; ++q) {
            const unsigned u = (q == 0) ? pk.x : (q == 1) ? pk.y : (q == 2) ? pk.z : pk.w;
            // w from low 16 bits (F2F reads low half directly)
            const float w = __half2float(__ushort_as_half((unsigned short)u));
            uint64_t w2;
            asm("mov.b64 %0, {%1, %1};" : "=l"(w2) : "f"(w));
            // byte offset = u >> 16  (pre-scaled ix<<4)
            const uint4 raw = *reinterpret_cast<const uint4*>(
                reinterpret_cast<const char*>(xs) + (u >> 16));
            float2 f0 = __half22float2(*reinterpret_cast<const __half2*>(&raw.x));
            float2 f1 = __half22float2(*reinterpret_cast<const __half2*>(&raw.y));
            float2 f2 = __half22float2(*reinterpret_cast<const __half2*>(&raw.z));
            float2 f3 = __half22float2(*reinterpret_cast<const __half2*>(&raw.w));
            uint64_t p0, p1, p2, p3;
            asm("mov.b64 %0, {%1, %2};" : "=l"(p0) : "f"(f0.x), "f"(f0.y));
            asm("mov.b64 %0, {%1, %2};" : "=l"(p1) : "f"(f1.x), "f"(f1.y));
            asm("mov.b64 %0, {%1, %2};" : "=l"(p2) : "f"(f2.x), "f"(f2.y));
            asm("mov.b64 %0, {%1, %2};" : "=l"(p3) : "f"(f3.x), "f"(f3.y));
            asm("fma.rn.f32x2 %0, %1, %2, %0;" : "+l"(acc01) : "l"(w2), "l"(p0));
            asm("fma.rn.f32x2 %0, %1, %2, %0;" : "+l"(acc23) : "l"(w2), "l"(p1));
            asm("fma.rn.f32x2 %0, %1, %2, %0;" : "+l"(acc45) : "l"(w2), "l"(p2));
            asm("fma.rn.f32x2 %0, %1, %2, %0;" : "+l"(acc67) : "l"(w2), "l"(p3));
        }
    }

    float accs[BT];
    asm("mov.b64 {%0, %1}, %2;" : "=f"(accs[0]), "=f"(accs[1]) : "l"(acc01));
    asm("mov.b64 {%0, %1}, %2;" : "=f"(accs[2]), "=f"(accs[3]) : "l"(acc23));
    asm("mov.b64 {%0, %1}, %2;" : "=f"(accs[4]), "=f"(accs[5]) : "l"(acc45));
    asm("mov.b64 {%0, %1}, %2;" : "=f"(accs[6]), "=f"(accs[7]) : "l"(acc67));

    float sv[BT];
    #pragma unroll
    for (int j = 0; j < BT; ++j) {
        float p = accs[j] + bias;
        float a = p >= 0.f ? p : NEG * p;
        dend_out[(size_t)(b0 + j) * NUM_DEND + d] = a;
        sv[j] = a * cwv;
    }

    #pragma unroll
    for (int off = 8; off >= 1; off >>= 1) {
        #pragma unroll
        for (int j = 0; j < BT; ++j)
            sv[j] += __shfl_xor_sync(0xffffffffu, sv[j], off);
    }

    if ((tid & (BRANCH - 1)) == 0) {
        const int n  = d >> 4;
        const float nb = somab[n];
        #pragma unroll
        for (int j = 0; j < BT; ++j) {
            float p = sv[j] + nb;
            soma_out[(size_t)(b0 + j) * SOMA + n] = p >= 0.f ? p : NEG * p;
        }
    }
}

extern "C" void kernel_launch(void* const* d_in, const int* in_sizes, int n_in,
                              void* d_out, int out_size)
{
    const float* x     = (const float*)d_in[0];
    const int*   idx   = (const int*)  d_in[1];
    const float* sw    = (const float*)d_in[2];
    const float* sb    = (const float*)d_in[3];
    const float* cw    = (const float*)d_in[4];
    const float* somab = (const float*)d_in[5];

    float* out      = (float*)d_out;
    float* soma_out = out;                          // [256, 2048]
    float* dend_out = out + (size_t)BATCH * SOMA;   // [256, 32768]

    prep_fused<<<XB + PB, PREP_THREADS>>>(x, idx, sw);

    const size_t smem = XS_BYTES;  // 64 KB dynamic
    cudaFuncSetAttribute(dend_kernel, cudaFuncAttributeMaxDynamicSharedMemorySize, (int)smem);

    dim3 grid(NUM_DEND / DT, BATCH / BT);
    dend_kernel<<<grid, NTHREADS, smem>>>(sb, cw, somab, soma_out, dend_out);
}

// round 10
// speedup vs baseline: 1.0254x; 1.0254x over previous
#include <cuda_runtime.h>
#include <cuda_fp16.h>
#include <cstdint>

#define BATCH      256
#define INPUT_DIM  4096
#define SOMA       2048
#define BRANCH     16
#define NUM_DEND   (SOMA * BRANCH)   // 32768
#define SAMPLE     32
#define NEG        0.1f

#define BT         8                 // batches per block (4x half2 = 16B per x element)
#define NBG        (BATCH / BT)      // 32 batch groups
#define DT         512
#define NTHREADS   512

#define PREP_THREADS 256
#define XB   ((NBG * 2 * INPUT_DIM) / PREP_THREADS)   // 1024 blocks for x prep
#define PB   (NUM_DEND / PREP_THREADS)                // 128 blocks for pack prep

#define XS_BYTES (INPUT_DIM * 16)    // 64 KB

// Scratch (allocation-free rule: __device__ globals)
// pk word layout: [15:0] = w (fp16 bits), [31:16] = ix<<4 (byte offset)
__device__ uint4  g_pk[(SAMPLE/4) * NUM_DEND];     // [s4][d], 4 MB
__device__ uint4  g_xprep[NBG * INPUT_DIM];        // [bg][i]: 8 batches as 4x half2, 2 MB

__device__ __forceinline__ uint32_t smem_u32(const void* p) {
    uint32_t a;
    asm("{ .reg .u64 t; cvta.to.shared.u64 t, %1; cvt.u32.u64 %0, t; }" : "=r"(a) : "l"(p));
    return a;
}

// ---- fused pre-pass: x packing (blocks < XB) + idx/w pack-sort (blocks >= XB) ----
__global__ void prep_fused(const float* __restrict__ x,
                           const int*   __restrict__ idx,
                           const float* __restrict__ sw)
{
    // Allow the dependent (main) kernel to begin launching; its
    // griddepcontrol.wait blocks until this grid fully completes.
    asm volatile("griddepcontrol.launch_dependents;");

    __shared__ unsigned buf[SAMPLE * PREP_THREADS];  // 32 KB (used by pack part)
    const int tid = threadIdx.x;

    if (blockIdx.x < XB) {
        // ---- pack x into batch-interleaved fp16 ----
        int t  = blockIdx.x * PREP_THREADS + tid;     // 0 .. NBG*2*INPUT_DIM-1
        int bg = t / (2 * INPUT_DIM);
        int r  = t - bg * 2 * INPUT_DIM;
        int h  = r / INPUT_DIM;
        int i  = r - h * INPUT_DIM;

        const float* xr = x + ((size_t)bg * BT + h * 4) * INPUT_DIM + i;
        __half2 a = __floats2half2_rn(xr[0],             xr[INPUT_DIM]);
        __half2 b = __floats2half2_rn(xr[2 * INPUT_DIM], xr[3 * INPUT_DIM]);
        uint2 v;
        v.x = *reinterpret_cast<unsigned*>(&a);
        v.y = *reinterpret_cast<unsigned*>(&b);
        reinterpret_cast<uint2*>(g_xprep)[(size_t)(bg * INPUT_DIM + i) * 2 + h] = v;
        return;
    }

    // ---- pack {off16 = ix<<4, w fp16} with FIXED-SLOT bank-class schedule ----
    const int d = (blockIdx.x - XB) * PREP_THREADS + tid;

    const int4*   ir = reinterpret_cast<const int4*>(idx) + (size_t)d * (SAMPLE/4);
    const float4* wr = reinterpret_cast<const float4*>(sw) + (size_t)d * (SAMPLE/4);

    // Load + pack all 32 elements (static indices -> registers)
    unsigned pkv[SAMPLE];
    #pragma unroll
    for (int s4 = 0; s4 < SAMPLE/4; ++s4) {
        const int4   i4 = ir[s4];
        const float4 w4 = wr[s4];
        #pragma unroll
        for (int q = 0; q < 4; ++q) {
            const int   ix = (q == 0) ? i4.x : (q == 1) ? i4.y : (q == 2) ? i4.z : i4.w;
            const float w  = (q == 0) ? w4.x : (q == 1) ? w4.y : (q == 2) ? w4.z : w4.w;
            pkv[4*s4 + q] = (unsigned)__half_as_ushort(__float2half_rn(w))
                          | ((unsigned)ix << 20);            // (ix<<4) in high 16
        }
    }

    // Pass A: class c (= ix&7 = bits [22:20]) owns slots 4c..4c+3
    unsigned long long fill = 0ull;
    unsigned unplaced = 0u;
    #pragma unroll
    for (int e = 0; e < SAMPLE; ++e) {
        const int c = (int)((pkv[e] >> 20) & 7u);
        const int p = (int)((fill >> (8 * c)) & 0xff);
        if (p < 4) {
            fill += 1ull << (8 * c);
            buf[(4 * c + p) * PREP_THREADS + tid] = pkv[e];
        } else {
            unplaced |= 1u << e;
        }
    }
    // Pass B: overflow fills deficit slots (static pkv indices)
    {
        int cslot = 0;
        #pragma unroll
        for (int e = 0; e < SAMPLE; ++e) {
            if ((unplaced >> e) & 1u) {
                while (((fill >> (8 * cslot)) & 0xffull) >= 4) ++cslot;
                const int p = (int)((fill >> (8 * cslot)) & 0xff);
                fill += 1ull << (8 * cslot);
                buf[(4 * cslot + p) * PREP_THREADS + tid] = pkv[e];
            }
        }
    }

    // Output with per-lane rotation so quarter-warp classes are staggered
    const int rot = 4 * (d & 7);
    #pragma unroll
    for (int s4 = 0; s4 < SAMPLE/4; ++s4) {
        uint4 p;
        p.x = buf[(((4*s4 + 0) + rot) & 31) * PREP_THREADS + tid];
        p.y = buf[(((4*s4 + 1) + rot) & 31) * PREP_THREADS + tid];
        p.z = buf[(((4*s4 + 2) + rot) & 31) * PREP_THREADS + tid];
        p.w = buf[(((4*s4 + 3) + rot) & 31) * PREP_THREADS + tid];
        g_pk[s4 * NUM_DEND + d] = p;
    }
}

// ---- main kernel ----
__global__ __launch_bounds__(NTHREADS, 2)
void dend_kernel(const float* __restrict__ sb,
                 const float* __restrict__ cw,
                 const float* __restrict__ somab,
                 float* __restrict__ soma_out,
                 float* __restrict__ dend_out)
{
    extern __shared__ uint4 xs[];   // [INPUT_DIM] = 64 KB
    __shared__ __align__(8) uint64_t mbar;

    const int bg  = blockIdx.y;
    const int b0  = bg * BT;
    const int d0  = blockIdx.x * DT;
    const int tid = threadIdx.x;

    const uint32_t mbar_a = smem_u32(&mbar);
    const uint32_t xs_a   = smem_u32(xs);

    if (tid == 0) {
        asm volatile("mbarrier.init.shared::cta.b64 [%0], 1;" :: "r"(mbar_a) : "memory");
    }
    __syncthreads();

    // PDL: block until prep_fused fully completes (memory visible)
    asm volatile("griddepcontrol.wait;" ::: "memory");

    if (tid == 0) {
        asm volatile("mbarrier.arrive.expect_tx.shared::cta.b64 _, [%0], %1;"
                     :: "r"(mbar_a), "r"((unsigned)XS_BYTES) : "memory");
        asm volatile("cp.async.bulk.shared::cta.global.mbarrier::complete_tx::bytes "
                     "[%0], [%1], %2, [%3];"
                     :: "r"(xs_a), "l"(g_xprep + (size_t)bg * INPUT_DIM),
                        "r"((unsigned)XS_BYTES), "r"(mbar_a) : "memory");
    }

    const int d = d0 + tid;

    // Prefetch first pk + scalars while TMA fills smem
    const uint4 pk0  = g_pk[d];
    const float bias = sb[d];
    const float cwv  = cw[d];   // cable_weights flattened [soma][branch] == index d

    // Wait for bulk copy completion (phase 0)
    {
        unsigned done;
        asm volatile(
            "{\n\t.reg .pred p;\n\t"
            "mbarrier.try_wait.parity.acquire.cta.shared::cta.b64 p, [%1], 0;\n\t"
            "selp.b32 %0, 1, 0, p;\n\t}"
            : "=r"(done) : "r"(mbar_a) : "memory");
        while (!done) {
            asm volatile(
                "{\n\t.reg .pred p;\n\t"
                "mbarrier.try_wait.parity.acquire.cta.shared::cta.b64 p, [%1], 0, 0x989680;\n\t"
                "selp.b32 %0, 1, 0, p;\n\t}"
                : "=r"(done) : "r"(mbar_a) : "memory");
        }
    }

    float acc0 = 0.f, acc1 = 0.f, acc2 = 0.f, acc3 = 0.f;
    float acc4 = 0.f, acc5 = 0.f, acc6 = 0.f, acc7 = 0.f;

    #pragma unroll
    for (int s4 = 0; s4 < SAMPLE / 4; ++s4) {
        const uint4 pk = (s4 == 0) ? pk0 : g_pk[s4 * NUM_DEND + d];   // coalesced

        #pragma unroll
        for (int q = 0; q < 4; ++q) {
            const unsigned u = (q == 0) ? pk.x : (q == 1) ? pk.y : (q == 2) ? pk.z : pk.w;
            // w from low 16 bits (direct F2F, no shift)
            const float w = __half2float(__ushort_as_half((unsigned short)u));
            // byte offset = u >> 16  (pre-scaled ix<<4)
            const uint4 raw = *reinterpret_cast<const uint4*>(
                reinterpret_cast<const char*>(xs) + (u >> 16));
            float2 f0 = __half22float2(*reinterpret_cast<const __half2*>(&raw.x));
            float2 f1 = __half22float2(*reinterpret_cast<const __half2*>(&raw.y));
            float2 f2 = __half22float2(*reinterpret_cast<const __half2*>(&raw.z));
            float2 f3 = __half22float2(*reinterpret_cast<const __half2*>(&raw.w));
            acc0 = fmaf(w, f0.x, acc0); acc1 = fmaf(w, f0.y, acc1);
            acc2 = fmaf(w, f1.x, acc2); acc3 = fmaf(w, f1.y, acc3);
            acc4 = fmaf(w, f2.x, acc4); acc5 = fmaf(w, f2.y, acc5);
            acc6 = fmaf(w, f3.x, acc6); acc7 = fmaf(w, f3.y, acc7);
        }
    }

    float accs[BT] = {acc0, acc1, acc2, acc3, acc4, acc5, acc6, acc7};
    float sv[BT];
    #pragma unroll
    for (int j = 0; j < BT; ++j) {
        float p = accs[j] + bias;
        float a = p >= 0.f ? p : NEG * p;
        dend_out[(size_t)(b0 + j) * NUM_DEND + d] = a;
        sv[j] = a * cwv;
    }

    #pragma unroll
    for (int off = 8; off >= 1; off >>= 1) {
        #pragma unroll
        for (int j = 0; j < BT; ++j)
            sv[j] += __shfl_xor_sync(0xffffffffu, sv[j], off);
    }

    if ((tid & (BRANCH - 1)) == 0) {
        const int n  = d >> 4;
        const float nb = somab[n];
        #pragma unroll
        for (int j = 0; j < BT; ++j) {
            float p = sv[j] + nb;
            soma_out[(size_t)(b0 + j) * SOMA + n] = p >= 0.f ? p : NEG * p;
        }
    }
}

extern "C" void kernel_launch(void* const* d_in, const int* in_sizes, int n_in,
                              void* d_out, int out_size)
{
    const float* x     = (const float*)d_in[0];
    const int*   idx   = (const int*)  d_in[1];
    const float* sw    = (const float*)d_in[2];
    const float* sb    = (const float*)d_in[3];
    const float* cw    = (const float*)d_in[4];
    const float* somab = (const float*)d_in[5];

    float* out      = (float*)d_out;
    float* soma_out = out;                          // [256, 2048]
    float* dend_out = out + (size_t)BATCH * SOMA;   // [256, 32768]

    prep_fused<<<XB + PB, PREP_THREADS>>>(x, idx, sw);

    const size_t smem = XS_BYTES;  // 64 KB dynamic
    cudaFuncSetAttribute(dend_kernel, cudaFuncAttributeMaxDynamicSharedMemorySize, (int)smem);

    // Launch main kernel with Programmatic Dependent Launch so its prologue
    // overlaps prep_fused's tail; griddepcontrol.wait provides the ordering.
    cudaLaunchConfig_t cfg = {};
    cfg.gridDim  = dim3(NUM_DEND / DT, BATCH / BT, 1);
    cfg.blockDim = dim3(NTHREADS, 1, 1);
    cfg.dynamicSmemBytes = smem;
    cfg.stream = 0;
    cudaLaunchAttribute attr[1];
    attr[0].id = cudaLaunchAttributeProgrammaticStreamSerialization;
    attr[0].val.programmaticStreamSerializationAllowed = 1;
    cfg.attrs = attr;
    cfg.numAttrs = 1;
    cudaLaunchKernelEx(&cfg, dend_kernel, sb, cw, somab, soma_out, dend_out);
}